// round 7
// baseline (speedup 1.0000x reference)
#include <cuda_runtime.h>
#include <cstdint>

// CRF Viterbi decode: B=128, T=1024, K=128.
// Grid = 64 CTAs x 256 threads; each CTA runs TWO independent batch groups
// (g = tid>>7, batch = 2*blockIdx.x+g) with per-group NAMED barriers so the
// two serial recurrences interleave on the SM and hide each other's
// barrier/chain latency bubbles.
// Per group: thread per output column j; each thread reduces ALL 128 i's
// (broadcast LDS.128 state, f32x2 adds, transitions in 64 u64 regs, 8 accs),
// no cross-thread reduction. Double-buffered state => one group-barrier per
// step. Logits cp.async double-buffered. History -> 64MB scratch. Backtrack:
// group warp 0 walks with double-buffered cp.async 32-row block staging;
// IMNMX local argmax + integer REDUX (exact first-index tie-break).

#define BB 128
#define TT 1024
#define KK 128
#define TC_STRIDE 132
#define NTHREADS 256
#define GSIZE 128
#define BR 32                 // backtrack block rows

__device__ float g_state[(size_t)BB * TT * KK];

struct __align__(16) Group {
    float spad[2][KK];              // double-buffered state
    float logit[2][16][KK];         // double-buffered logit staging
    float block[2][BR * KK];        // double-buffered backtrack staging
    int   tags[TT];
    int   lasttag;
    int   pad[3];
};
struct __align__(16) SmemLayout {
    float transC[KK * TC_STRIDE];   // transC[j*132 + i] = T[i][j] (shared)
    Group grp[2];
};

__device__ __forceinline__ unsigned smem_u32(const void* p) {
    return (unsigned)__cvta_generic_to_shared(p);
}
__device__ __forceinline__ void cp_async16(unsigned dst, const void* src) {
    asm volatile("cp.async.cg.shared.global [%0], [%1], 16;" :: "r"(dst), "l"(src));
}
__device__ __forceinline__ unsigned f32_mono_u32(float x) {
    unsigned b = __float_as_uint(x);
    return b ^ (unsigned)(((int)b >> 31) | 0x80000000);
}
// Per-group named barrier (ids 1 and 2; 0 reserved for __syncthreads)
__device__ __forceinline__ void gbar(int g) {
    asm volatile("bar.sync %0, %1;" :: "r"(1 + g), "r"(GSIZE) : "memory");
}

__global__ void __launch_bounds__(NTHREADS, 1)
crf_viterbi_kernel(const float* __restrict__ logits,
                   const int*   __restrict__ lens,
                   const float* __restrict__ trans,
                   float*       __restrict__ out)
{
    extern __shared__ char smraw[];
    SmemLayout& s = *reinterpret_cast<SmemLayout*>(smraw);

    const int tid  = threadIdx.x;
    const int g    = tid >> 7;          // group 0/1
    const int gtid = tid & (GSIZE - 1); // thread id within group
    const int gw   = gtid >> 5;         // warp within group (0..3)
    const int lane = tid & 31;
    const int j    = gtid;              // output column owned by this thread
    const int bb   = blockIdx.x * 2 + g;
    const int len  = lens[bb];
    Group& gr = s.grp[g];

    // ---- transC staging (whole CTA cooperates; init-only) ----
    for (int idx = tid * 4; idx < KK * KK; idx += NTHREADS * 4) {
        float4 v = *reinterpret_cast<const float4*>(trans + idx);
        int i  = idx >> 7;
        int jj = idx & (KK - 1);
        s.transC[(jj + 0) * TC_STRIDE + i] = v.x;
        s.transC[(jj + 1) * TC_STRIDE + i] = v.y;
        s.transC[(jj + 2) * TC_STRIDE + i] = v.z;
        s.transC[(jj + 3) * TC_STRIDE + i] = v.w;
    }

    // ---- init state = logits[bb, 0, :] ----
    {
        float v = logits[((size_t)bb * TT) * KK + gtid];
        gr.spad[0][gtid] = v;
        g_state[((size_t)bb * TT) * KK + gtid] = v;
    }

    // ---- prologue: stage logit rows 1..16 into buffer 0 ----
    {
        const float* base = logits + (size_t)bb * TT * KK + lane * 4;
        #pragma unroll
        for (int k = 0; k < 4; ++k) {
            int ridx = gw + 4 * k;          // row-in-epoch 0..15
            int r = 1 + ridx;  if (r > TT - 1) r = TT - 1;
            cp_async16(smem_u32(&gr.logit[0][ridx][lane * 4]),
                       base + (size_t)r * KK);
        }
        asm volatile("cp.async.commit_group;");
    }
    __syncthreads();   // transC visible to everyone (once)

    // ---- this thread's 128 transitions (column j) from SMEM, 64 f32x2 ----
    unsigned long long t2[64];
    #pragma unroll
    for (int m = 0; m < 64; ++m) {
        float2 tp = *reinterpret_cast<const float2*>(
            &s.transC[j * TC_STRIDE + 2 * m]);
        asm("mov.b64 %0, {%1, %2};" : "=l"(t2[m]) : "f"(tp.x), "f"(tp.y));
    }

    const unsigned sb0 = smem_u32(&gr.spad[0][0]);
    const unsigned sb1 = smem_u32(&gr.spad[1][0]);
    int pr = 0;

    // ================= forward pass (value-only) =================
    for (int t = 1; t < len; ++t) {
        const int rel = t - 1;
        if ((rel & 15) == 0) {
            int ge = rel >> 4;
            int base_row = 1 + (ge + 1) * 16;
            int nb = (ge + 1) & 1;
            const float* base = logits + (size_t)bb * TT * KK + lane * 4;
            #pragma unroll
            for (int k = 0; k < 4; ++k) {
                int ridx = gw + 4 * k;
                int r = base_row + ridx;  if (r > TT - 1) r = TT - 1;
                cp_async16(smem_u32(&gr.logit[nb][ridx][lane * 4]),
                           base + (size_t)r * KK);
            }
            asm volatile("cp.async.commit_group;");
            asm volatile("cp.async.wait_group 1;");
            gbar(g);
        }

        const unsigned sbr = pr ? sb1 : sb0;
        const float lg = gr.logit[(rel >> 4) & 1][rel & 15][j];

        // 128 candidates: 32x broadcast LDS.128, 64x add.rn.f32x2, 8-acc tree
        float a0, a1, a2, a3, a4, a5, a6, a7;
        #pragma unroll
        for (int u = 0; u < 32; ++u) {
            unsigned long long p0, p1, c0, c1;
            asm volatile("ld.shared.v2.u64 {%0, %1}, [%2];"
                         : "=l"(p0), "=l"(p1) : "r"(sbr + 16 * u));
            asm("add.rn.f32x2 %0, %1, %2;" : "=l"(c0) : "l"(p0), "l"(t2[2 * u]));
            asm("add.rn.f32x2 %0, %1, %2;" : "=l"(c1) : "l"(p1), "l"(t2[2 * u + 1]));
            float x0, x1, x2, x3;
            asm("mov.b64 {%0, %1}, %2;" : "=f"(x0), "=f"(x1) : "l"(c0));
            asm("mov.b64 {%0, %1}, %2;" : "=f"(x2), "=f"(x3) : "l"(c1));
            if (u == 0)      { a0 = x0; a1 = x1; a2 = x2; a3 = x3; }
            else if (u == 1) { a4 = x0; a5 = x1; a6 = x2; a7 = x3; }
            else if (u & 1)  { a4 = fmaxf(a4, x0); a5 = fmaxf(a5, x1);
                               a6 = fmaxf(a6, x2); a7 = fmaxf(a7, x3); }
            else             { a0 = fmaxf(a0, x0); a1 = fmaxf(a1, x1);
                               a2 = fmaxf(a2, x2); a3 = fmaxf(a3, x3); }
        }
        float b0 = fmaxf(a0, a4), b1 = fmaxf(a1, a5);
        float b2 = fmaxf(a2, a6), b3 = fmaxf(a3, a7);
        float best = fmaxf(fmaxf(b0, b1), fmaxf(b2, b3)) + lg;

        gr.spad[pr ^ 1][j] = best;
        g_state[((size_t)bb * TT + t) * KK + j] = best;
        pr ^= 1;
        gbar(g);
    }
    asm volatile("cp.async.wait_all;");

    // ---- last tag = argmax_j final state (group warp 0, first-index) ----
    if (gw == 0) {
        const float* st = gr.spad[pr];
        unsigned u0 = f32_mono_u32(st[4 * lane + 0]);
        unsigned u1 = f32_mono_u32(st[4 * lane + 1]);
        unsigned u2 = f32_mono_u32(st[4 * lane + 2]);
        unsigned u3 = f32_mono_u32(st[4 * lane + 3]);
        unsigned lm = max(max(u0, u1), max(u2, u3));
        unsigned gm = __reduce_max_sync(0xffffffffu, lm);
        unsigned cand = (u0 == gm) ? (unsigned)(4 * lane)
                      : (u1 == gm) ? (unsigned)(4 * lane + 1)
                      : (u2 == gm) ? (unsigned)(4 * lane + 2)
                      : (u3 == gm) ? (unsigned)(4 * lane + 3)
                      : 0xffffffffu;
        unsigned bi = __reduce_min_sync(0xffffffffu, cand);
        if (lane == 0) gr.lasttag = (int)bi;
    }
    gbar(g);
    const int lt = gr.lasttag;

    // tail fill: tags[t] = last_tag for t >= len-1
    for (int t = len - 1 + gtid; t < TT; t += GSIZE) gr.tags[t] = lt;

    // ================= backtrack (double-buffered staging + walk) =========
    int cur = lt;
    int hi = len - 2;
    int bb2 = 0;
    if (hi >= 0) {
        {   // stage first block
            int lo2 = hi - (BR - 1); if (lo2 < 0) lo2 = 0;
            int n = (hi - lo2 + 1) * KK;
            const float* src = g_state + ((size_t)bb * TT + lo2) * KK;
            for (int idx = gtid * 4; idx < n; idx += GSIZE * 4)
                cp_async16(smem_u32(&gr.block[0][idx]), src + idx);
            asm volatile("cp.async.commit_group;");
        }
        while (hi >= 0) {
            int lo = hi - (BR - 1); if (lo < 0) lo = 0;
            int nhi = lo - 1;
            if (nhi >= 0) {
                int lo2 = nhi - (BR - 1); if (lo2 < 0) lo2 = 0;
                int n = (nhi - lo2 + 1) * KK;
                const float* src = g_state + ((size_t)bb * TT + lo2) * KK;
                for (int idx = gtid * 4; idx < n; idx += GSIZE * 4)
                    cp_async16(smem_u32(&gr.block[bb2 ^ 1][idx]), src + idx);
                asm volatile("cp.async.commit_group;");
                asm volatile("cp.async.wait_group 1;");
            } else {
                asm volatile("cp.async.wait_group 0;");
            }
            gbar(g);

            if (gtid < 32) {
                const float* blk = gr.block[bb2];
                float4 sv = *reinterpret_cast<const float4*>(
                    &blk[(hi - lo) * KK + 4 * lane]);
                for (int t = hi; t >= lo; --t) {
                    float4 tv = *reinterpret_cast<const float4*>(
                        &s.transC[cur * TC_STRIDE + 4 * lane]);
                    float4 svn;
                    if (t > lo)
                        svn = *reinterpret_cast<const float4*>(
                            &blk[(t - 1 - lo) * KK + 4 * lane]);
                    unsigned u0 = f32_mono_u32(sv.x + tv.x);
                    unsigned u1 = f32_mono_u32(sv.y + tv.y);
                    unsigned u2 = f32_mono_u32(sv.z + tv.z);
                    unsigned u3 = f32_mono_u32(sv.w + tv.w);
                    unsigned lm = max(max(u0, u1), max(u2, u3));
                    unsigned gm = __reduce_max_sync(0xffffffffu, lm);
                    unsigned cand = (u0 == gm) ? (unsigned)(4 * lane)
                                  : (u1 == gm) ? (unsigned)(4 * lane + 1)
                                  : (u2 == gm) ? (unsigned)(4 * lane + 2)
                                  : (u3 == gm) ? (unsigned)(4 * lane + 3)
                                  : 0xffffffffu;
                    cur = (int)__reduce_min_sync(0xffffffffu, cand);
                    if (lane == 0) gr.tags[t] = cur;
                    sv = svn;
                }
            }
            gbar(g);
            hi = nhi;
            bb2 ^= 1;
        }
    }
    gbar(g);  // covers len==1 path (tags tail-fill -> output)

    // ================= one-hot output =================
    float* ob = out + (size_t)bb * TT * KK;
    for (int it = 0; it < TT / 4; ++it) {
        int t = it * 4 + gw;
        int tg = gr.tags[t];
        float4 v;
        v.x = (tg == 4 * lane + 0) ? 1.0f : 0.0f;
        v.y = (tg == 4 * lane + 1) ? 1.0f : 0.0f;
        v.z = (tg == 4 * lane + 2) ? 1.0f : 0.0f;
        v.w = (tg == 4 * lane + 3) ? 1.0f : 0.0f;
        *reinterpret_cast<float4*>(ob + (size_t)t * KK + 4 * lane) = v;
    }
}

extern "C" void kernel_launch(void* const* d_in, const int* in_sizes, int n_in,
                              void* d_out, int out_size) {
    const float* logits = (const float*)d_in[0];
    const int*   lens   = (const int*)d_in[1];
    const float* trans  = (const float*)d_in[2];
    float*       out    = (float*)d_out;

    cudaFuncSetAttribute(crf_viterbi_kernel,
                         cudaFuncAttributeMaxDynamicSharedMemorySize,
                         (int)sizeof(SmemLayout));
    crf_viterbi_kernel<<<BB / 2, NTHREADS, sizeof(SmemLayout)>>>(
        logits, lens, trans, out);
}

// round 8
// speedup vs baseline: 1.3859x; 1.3859x over previous
#include <cuda_runtime.h>
#include <cstdint>

// CRF Viterbi decode: B=128, T=1024, K=128. One CTA (128 threads) per batch.
// R8: forward step has NO global stores. State history accumulates in a
// 32-row SMEM ring; every 16 steps one thread flushes the completed 16-row
// half to the 64MB gmem scratch with a single cp.async.bulk (smem->gmem),
// pipelined one epoch deep (wait_group.read 1). The per-step __syncthreads
// therefore drains only one STS, not an STG->L2 round trip.
// Forward math unchanged from R6: thread per column j, 32x broadcast
// LDS.128 of state, 64x add.rn.f32x2 vs transitions in 64 u64 regs,
// 8-accumulator FMNMX tree. Backtrack: warp 0 walks with double-buffered
// cp.async 64-row block staging; IMNMX local argmax + integer REDUX
// (exact first-index tie-break matching jnp.argmax). One-hot f32 out.

#define BB 128
#define TT 1024
#define KK 128
#define TC_STRIDE 132
#define NTHREADS 128

__device__ float g_state[(size_t)BB * TT * KK];

struct __align__(16) SmemLayout {
    float transC[KK * TC_STRIDE];   // transC[j*132 + i] = T[i][j]
    float hist[32][KK];             // state-history ring (two 16-row halves)
    float logit[2][16][KK];         // double-buffered logit staging
    float block[2][64 * KK];        // double-buffered backtrack staging
    int   tags[TT];
    int   lasttag;
};

__device__ __forceinline__ unsigned smem_u32(const void* p) {
    return (unsigned)__cvta_generic_to_shared(p);
}
__device__ __forceinline__ void cp_async16(unsigned dst, const void* src) {
    asm volatile("cp.async.cg.shared.global [%0], [%1], 16;" :: "r"(dst), "l"(src));
}
__device__ __forceinline__ void bulk_flush(const float* gdst, unsigned ssrc,
                                           unsigned bytes) {
    asm volatile("fence.proxy.async.shared::cta;");
    asm volatile("cp.async.bulk.global.shared::cta.bulk_group [%0], [%1], %2;"
                 :: "l"((unsigned long long)(uintptr_t)gdst), "r"(ssrc), "r"(bytes)
                 : "memory");
    asm volatile("cp.async.bulk.commit_group;");
}
__device__ __forceinline__ unsigned f32_mono_u32(float x) {
    unsigned b = __float_as_uint(x);
    return b ^ (unsigned)(((int)b >> 31) | 0x80000000);
}

__global__ void __launch_bounds__(NTHREADS, 1)
crf_viterbi_kernel(const float* __restrict__ logits,
                   const int*   __restrict__ lens,
                   const float* __restrict__ trans,
                   float*       __restrict__ out)
{
    extern __shared__ char smraw[];
    SmemLayout& s = *reinterpret_cast<SmemLayout*>(smraw);

    const int b    = blockIdx.x;
    const int tid  = threadIdx.x;
    const int w    = tid >> 5;         // 4 warps
    const int lane = tid & 31;
    const int j    = tid;              // output column owned by this thread
    const int len  = lens[b];

    // ---- transC staging (vectorized read, strided scalar STS; init-only) ----
    for (int idx = tid * 4; idx < KK * KK; idx += NTHREADS * 4) {
        float4 v = *reinterpret_cast<const float4*>(trans + idx);
        int i  = idx >> 7;
        int jj = idx & (KK - 1);
        s.transC[(jj + 0) * TC_STRIDE + i] = v.x;
        s.transC[(jj + 1) * TC_STRIDE + i] = v.y;
        s.transC[(jj + 2) * TC_STRIDE + i] = v.z;
        s.transC[(jj + 3) * TC_STRIDE + i] = v.w;
    }

    // ---- init state = logits[b, 0, :] -> hist slot 0 (no STG) ----
    s.hist[0][tid] = logits[((size_t)b * TT) * KK + tid];

    // ---- prologue: stage logit rows 1..16 into buffer 0 ----
    {
        const float* base = logits + (size_t)b * TT * KK + lane * 4;
        #pragma unroll
        for (int k = 0; k < 4; ++k) {
            int ridx = w + 4 * k;          // row-in-epoch 0..15
            int r = 1 + ridx;  if (r > TT - 1) r = TT - 1;
            cp_async16(smem_u32(&s.logit[0][ridx][lane * 4]), base + (size_t)r * KK);
        }
        asm volatile("cp.async.commit_group;");
    }
    __syncthreads();

    // ---- this thread's 128 transitions (column j) from SMEM, 64 f32x2 ----
    unsigned long long t2[64];
    #pragma unroll
    for (int m = 0; m < 64; ++m) {
        float2 tp = *reinterpret_cast<const float2*>(
            &s.transC[j * TC_STRIDE + 2 * m]);
        asm("mov.b64 %0, {%1, %2};" : "=l"(t2[m]) : "f"(tp.x), "f"(tp.y));
    }

    const unsigned histb = smem_u32(&s.hist[0][0]);
    const float* gbase = g_state + (size_t)b * TT * KK;

    // ================= forward pass (value-only, no STG) =================
    for (int t = 1; t < len; ++t) {
        const int rel = t - 1;

        // flush boundary: rows [t-16, t-1] complete -> bulk to gmem
        if ((t & 15) == 0) {
            if (tid == 0) {
                bulk_flush(gbase + (size_t)(t - 16) * KK,
                           histb + ((t - 16) & 31) * (KK * 4),
                           16 * KK * 4);
                asm volatile("cp.async.bulk.wait_group.read 1;");
            }
            __syncthreads();   // nobody overwrites a half still being read
        }
        // logit epoch boundary
        if ((rel & 15) == 0) {
            int g = rel >> 4;
            int base_row = 1 + (g + 1) * 16;
            int nb = (g + 1) & 1;
            const float* base = logits + (size_t)b * TT * KK + lane * 4;
            #pragma unroll
            for (int k = 0; k < 4; ++k) {
                int ridx = w + 4 * k;
                int r = base_row + ridx;  if (r > TT - 1) r = TT - 1;
                cp_async16(smem_u32(&s.logit[nb][ridx][lane * 4]),
                           base + (size_t)r * KK);
            }
            asm volatile("cp.async.commit_group;");
            asm volatile("cp.async.wait_group 1;");
            __syncthreads();
        }

        const unsigned sbr = histb + ((t - 1) & 31) * (KK * 4);
        const float lg = s.logit[(rel >> 4) & 1][rel & 15][j];

        // 128 candidates: 32x broadcast LDS.128, 64x add.rn.f32x2, 8-acc tree
        float a0, a1, a2, a3, a4, a5, a6, a7;
        #pragma unroll
        for (int u = 0; u < 32; ++u) {
            unsigned long long p0, p1, c0, c1;
            asm volatile("ld.shared.v2.u64 {%0, %1}, [%2];"
                         : "=l"(p0), "=l"(p1) : "r"(sbr + 16 * u));
            asm("add.rn.f32x2 %0, %1, %2;" : "=l"(c0) : "l"(p0), "l"(t2[2 * u]));
            asm("add.rn.f32x2 %0, %1, %2;" : "=l"(c1) : "l"(p1), "l"(t2[2 * u + 1]));
            float x0, x1, x2, x3;
            asm("mov.b64 {%0, %1}, %2;" : "=f"(x0), "=f"(x1) : "l"(c0));
            asm("mov.b64 {%0, %1}, %2;" : "=f"(x2), "=f"(x3) : "l"(c1));
            if (u == 0)      { a0 = x0; a1 = x1; a2 = x2; a3 = x3; }
            else if (u == 1) { a4 = x0; a5 = x1; a6 = x2; a7 = x3; }
            else if (u & 1)  { a4 = fmaxf(a4, x0); a5 = fmaxf(a5, x1);
                               a6 = fmaxf(a6, x2); a7 = fmaxf(a7, x3); }
            else             { a0 = fmaxf(a0, x0); a1 = fmaxf(a1, x1);
                               a2 = fmaxf(a2, x2); a3 = fmaxf(a3, x3); }
        }
        float b0 = fmaxf(a0, a4), b1 = fmaxf(a1, a5);
        float b2 = fmaxf(a2, a6), b3 = fmaxf(a3, a7);
        float best = fmaxf(fmaxf(b0, b1), fmaxf(b2, b3)) + lg;

        s.hist[t & 31][j] = best;           // STS only — no STG in the loop
        __syncthreads();
    }
    asm volatile("cp.async.wait_all;");
    __syncthreads();  // all rows written before tail flush reads them

    // ---- tail flush: rows [t_b, len-1] (1..16 rows), then full completion ----
    {
        int t_b = ((len - 1) >> 4) << 4;
        if (tid == 0) {
            bulk_flush(gbase + (size_t)t_b * KK,
                       histb + (t_b & 31) * (KK * 4),
                       (unsigned)(len - t_b) * (KK * 4));
            asm volatile("cp.async.bulk.wait_group 0;");
        }
    }

    // ---- last tag = argmax_j final state (warp 0, first-index tie-break) ----
    if (w == 0) {
        const float* st = s.hist[(len - 1) & 31];
        unsigned u0 = f32_mono_u32(st[4 * lane + 0]);
        unsigned u1 = f32_mono_u32(st[4 * lane + 1]);
        unsigned u2 = f32_mono_u32(st[4 * lane + 2]);
        unsigned u3 = f32_mono_u32(st[4 * lane + 3]);
        unsigned lm = max(max(u0, u1), max(u2, u3));
        unsigned gm = __reduce_max_sync(0xffffffffu, lm);
        unsigned cand = (u0 == gm) ? (unsigned)(4 * lane)
                      : (u1 == gm) ? (unsigned)(4 * lane + 1)
                      : (u2 == gm) ? (unsigned)(4 * lane + 2)
                      : (u3 == gm) ? (unsigned)(4 * lane + 3)
                      : 0xffffffffu;
        unsigned bi = __reduce_min_sync(0xffffffffu, cand);
        if (lane == 0) s.lasttag = (int)bi;
    }
    __syncthreads();   // orders everyone after tid0's bulk completion too
    const int lt = s.lasttag;

    // tail fill: tags[t] = last_tag for t >= len-1
    for (int t = len - 1 + tid; t < TT; t += NTHREADS) s.tags[t] = lt;

    // ================= backtrack (double-buffered staging + warp-0 walk) =====
    int cur = lt;
    int hi = len - 2;
    int bb2 = 0;
    if (hi >= 0) {
        {   // stage first block
            int lo2 = hi - 63; if (lo2 < 0) lo2 = 0;
            int n = (hi - lo2 + 1) * KK;
            const float* src = g_state + ((size_t)b * TT + lo2) * KK;
            for (int idx = tid * 4; idx < n; idx += NTHREADS * 4)
                cp_async16(smem_u32(&s.block[0][idx]), src + idx);
            asm volatile("cp.async.commit_group;");
        }
        while (hi >= 0) {
            int lo = hi - 63; if (lo < 0) lo = 0;
            int nhi = lo - 1;
            if (nhi >= 0) {
                int lo2 = nhi - 63; if (lo2 < 0) lo2 = 0;
                int n = (nhi - lo2 + 1) * KK;
                const float* src = g_state + ((size_t)b * TT + lo2) * KK;
                for (int idx = tid * 4; idx < n; idx += NTHREADS * 4)
                    cp_async16(smem_u32(&s.block[bb2 ^ 1][idx]), src + idx);
                asm volatile("cp.async.commit_group;");
                asm volatile("cp.async.wait_group 1;");
            } else {
                asm volatile("cp.async.wait_group 0;");
            }
            __syncthreads();

            if (tid < 32) {
                const float* blk = s.block[bb2];
                float4 sv = *reinterpret_cast<const float4*>(
                    &blk[(hi - lo) * KK + 4 * lane]);
                for (int t = hi; t >= lo; --t) {
                    float4 tv = *reinterpret_cast<const float4*>(
                        &s.transC[cur * TC_STRIDE + 4 * lane]);
                    float4 svn;
                    if (t > lo)
                        svn = *reinterpret_cast<const float4*>(
                            &blk[(t - 1 - lo) * KK + 4 * lane]);
                    unsigned u0 = f32_mono_u32(sv.x + tv.x);
                    unsigned u1 = f32_mono_u32(sv.y + tv.y);
                    unsigned u2 = f32_mono_u32(sv.z + tv.z);
                    unsigned u3 = f32_mono_u32(sv.w + tv.w);
                    unsigned lm = max(max(u0, u1), max(u2, u3));  // IMNMX tree
                    unsigned gm = __reduce_max_sync(0xffffffffu, lm);
                    unsigned cand = (u0 == gm) ? (unsigned)(4 * lane)
                                  : (u1 == gm) ? (unsigned)(4 * lane + 1)
                                  : (u2 == gm) ? (unsigned)(4 * lane + 2)
                                  : (u3 == gm) ? (unsigned)(4 * lane + 3)
                                  : 0xffffffffu;
                    cur = (int)__reduce_min_sync(0xffffffffu, cand);
                    if (lane == 0) s.tags[t] = cur;
                    sv = svn;
                }
            }
            __syncthreads();
            hi = nhi;
            bb2 ^= 1;
        }
    }
    __syncthreads();  // covers len==1 path (tags tail-fill -> output)

    // ================= one-hot output =================
    float* ob = out + (size_t)b * TT * KK;
    for (int it = 0; it < TT / 4; ++it) {
        int t = it * 4 + w;
        int tg = s.tags[t];
        float4 v;
        v.x = (tg == 4 * lane + 0) ? 1.0f : 0.0f;
        v.y = (tg == 4 * lane + 1) ? 1.0f : 0.0f;
        v.z = (tg == 4 * lane + 2) ? 1.0f : 0.0f;
        v.w = (tg == 4 * lane + 3) ? 1.0f : 0.0f;
        *reinterpret_cast<float4*>(ob + (size_t)t * KK + 4 * lane) = v;
    }
}

extern "C" void kernel_launch(void* const* d_in, const int* in_sizes, int n_in,
                              void* d_out, int out_size) {
    const float* logits = (const float*)d_in[0];
    const int*   lens   = (const int*)d_in[1];
    const float* trans  = (const float*)d_in[2];
    float*       out    = (float*)d_out;

    cudaFuncSetAttribute(crf_viterbi_kernel,
                         cudaFuncAttributeMaxDynamicSharedMemorySize,
                         (int)sizeof(SmemLayout));
    crf_viterbi_kernel<<<BB, NTHREADS, sizeof(SmemLayout)>>>(logits, lens, trans, out);
}